// round 12
// baseline (speedup 1.0000x reference)
#include <cuda_runtime.h>
#include <cstdint>
#include <cstddef>

#define BB 64
#define TT 512
#define II 128
#define HH 512
#define NCLS 5

#define F_HAVEA 1
#define F_HAVEB 2
#define F_GATEA 4

typedef unsigned long long u64;
typedef ulonglong2 ull2;

// Scratch — static __device__ arrays per allocation rules.
__device__ float g_xpA[(size_t)BB * TT * HH];
__device__ float g_xpB[(size_t)BB * TT * HH];
__device__ float g_ys[(size_t)BB * TT * HH];
// Multicast staging: [cluster8][rank8][slot4 = g*2+buf][256 floats] = 256KB
__device__ float g_stage[8 * 8 * 4 * 256];

// Cross-CTA coordination (reset by reset_counters before every mega launch).
__device__ int g_jcA;        // phase-A job queue head
__device__ int g_jcB;        // phase-B job queue head
__device__ int g_dA[4];      // phase-A completed-jobs count per t-block
__device__ int g_prog[64];   // recurrence progress per (cluster, rank)

// ---------------- packed f32x2 helpers ----------------
__device__ __forceinline__ u64 pk2(float x, float y) {
    u64 r; asm("mov.b64 %0, {%1,%2};" : "=l"(r) : "f"(x), "f"(y)); return r;
}
__device__ __forceinline__ float2 upk2(u64 v) {
    float2 f; asm("mov.b64 {%0,%1}, %2;" : "=f"(f.x), "=f"(f.y) : "l"(v)); return f;
}
__device__ __forceinline__ void fma2(u64 &d, u64 a, u64 b) {
    asm("fma.rn.f32x2 %0, %1, %2, %0;" : "+l"(d) : "l"(a), "l"(b));
}

// ---------------- cluster / mbarrier helpers ----------------
__device__ __forceinline__ uint32_t smem_u32(const void* p) {
    uint32_t a;
    asm("{ .reg .u64 t; cvta.to.shared.u64 t, %1; cvt.u32.u64 %0, t; }"
        : "=r"(a) : "l"(p));
    return a;
}
__device__ __forceinline__ void mbar_init(uint32_t addr, uint32_t count) {
    asm volatile("mbarrier.init.shared.b64 [%0], %1;" :: "r"(addr), "r"(count) : "memory");
}
__device__ __forceinline__ void mbar_expect_tx(uint32_t addr, uint32_t bytes) {
    asm volatile("mbarrier.arrive.expect_tx.shared.b64 _, [%0], %1;"
                 :: "r"(addr), "r"(bytes) : "memory");
}
// One multicast bulk copy: gmem -> same smem offset in every masked CTA,
// complete_tx of `bytes` delivered to each CTA's mbarrier at mbar offset.
__device__ __forceinline__ void bulk_copy_mc(uint32_t dst_smem, const void* src_gmem,
                                             uint32_t bytes, uint32_t mbar_smem,
                                             uint16_t mask) {
    asm volatile("cp.async.bulk.shared::cluster.global.mbarrier::complete_tx::bytes"
                 ".multicast::cluster [%0], [%1], %2, [%3], %4;"
                 :: "r"(dst_smem), "l"(src_gmem), "r"(bytes), "r"(mbar_smem), "h"(mask)
                 : "memory");
}
__device__ __forceinline__ void mbar_wait_cluster(uint32_t addr, uint32_t parity) {
    asm volatile(
        "{\n\t"
        ".reg .pred P;\n\t"
        "WLP%=:\n\t"
        "mbarrier.try_wait.parity.acquire.cluster.shared::cta.b64 P, [%0], %1, 0x989680;\n\t"
        "@P bra WDN%=;\n\t"
        "bra WLP%=;\n\t"
        "WDN%=:\n\t"
        "}"
        :: "r"(addr), "r"(parity) : "memory");
}
__device__ __forceinline__ void fence_proxy_async_all() {
    asm volatile("fence.proxy.async;" ::: "memory");
}
__device__ __forceinline__ void cluster_sync_full() {
    asm volatile("barrier.cluster.arrive.aligned;" ::: "memory");
    asm volatile("barrier.cluster.wait.aligned;" ::: "memory");
}

// =======================================================================
// One 128x128 GEMM tile: C = A[0:128,0:K] @ W[0:128,0:K]^T + b1 + b2.
// =======================================================================
__device__ __forceinline__ void gemm_tile(
    const float* __restrict__ A, const float* __restrict__ W,
    const float* __restrict__ b1, const float* __restrict__ b2,
    float* __restrict__ C, int K,
    u64 (*As2)[128], u64 (*Bs2)[128])
{
    const int tid = threadIdx.x;
    const int tx = tid & 15;
    const int ty = tid >> 4;
    const int r0  = tid >> 2;
    const int kq0 = tid & 3;

    u64 acc[8][8];
    #pragma unroll
    for (int i = 0; i < 8; i++)
        #pragma unroll
        for (int j = 0; j < 8; j++) acc[i][j] = 0ull;

    const float* pa0 = &A[(size_t)r0        * K + kq0 * 4];
    const float* pa1 = &A[(size_t)(64 + r0) * K + kq0 * 4];
    const float* pw0 = &W[(size_t)r0        * K + kq0 * 4];
    const float* pw1 = &W[(size_t)(64 + r0) * K + kq0 * 4];

    const int ktiles = K >> 4;
    float4 a0 = *(const float4*)pa0;
    float4 a1 = *(const float4*)pa1;
    float4 w0 = *(const float4*)pw0;
    float4 w1 = *(const float4*)pw1;

    for (int kt = 0; kt < ktiles; kt++) {
        __syncthreads();
        As2[kq0 * 2][r0]          = pk2(a0.x, a0.y);
        As2[kq0 * 2 + 1][r0]      = pk2(a0.z, a0.w);
        As2[kq0 * 2][64 + r0]     = pk2(a1.x, a1.y);
        As2[kq0 * 2 + 1][64 + r0] = pk2(a1.z, a1.w);
        Bs2[kq0 * 2][r0]          = pk2(w0.x, w0.y);
        Bs2[kq0 * 2 + 1][r0]      = pk2(w0.z, w0.w);
        Bs2[kq0 * 2][64 + r0]     = pk2(w1.x, w1.y);
        Bs2[kq0 * 2 + 1][64 + r0] = pk2(w1.z, w1.w);
        __syncthreads();

        if (kt + 1 < ktiles) {
            const int kb = (kt + 1) * 16;
            a0 = *(const float4*)(pa0 + kb);
            a1 = *(const float4*)(pa1 + kb);
            w0 = *(const float4*)(pw0 + kb);
            w1 = *(const float4*)(pw1 + kb);
        }

        #pragma unroll
        for (int k2 = 0; k2 < 8; k2++) {
            u64 af[8], bf[8];
            #pragma unroll
            for (int i = 0; i < 8; i++) af[i] = As2[k2][ty + 16 * i];
            #pragma unroll
            for (int j = 0; j < 8; j++) bf[j] = Bs2[k2][tx + 16 * j];
            #pragma unroll
            for (int i = 0; i < 8; i++)
                #pragma unroll
                for (int j = 0; j < 8; j++)
                    fma2(acc[i][j], af[i], bf[j]);
        }
    }

    float bias8[8];
    #pragma unroll
    for (int j = 0; j < 8; j++) {
        int n = tx + 16 * j;
        bias8[j] = b1[n] + b2[n];
    }
    #pragma unroll
    for (int i = 0; i < 8; i++) {
        const size_t m = (size_t)(ty + 16 * i);
        #pragma unroll
        for (int j = 0; j < 8; j++) {
            float2 p = upk2(acc[i][j]);
            C[m * HH + tx + 16 * j] = p.x + p.y + bias8[j];
        }
    }
}

// Run phase-B jobs (xproj of next layer from ys, K=512, gated on g_prog).
__device__ void run_phaseB(const float* __restrict__ ys,
                           const float* __restrict__ WihB,
                           const float* __restrict__ biB,
                           const float* __restrict__ bhB,
                           float* __restrict__ CB,
                           u64 (*As2)[128], u64 (*Bs2)[128])
{
    __shared__ int s_job;
    for (;;) {
        if (threadIdx.x == 0)
            s_job = atomicAdd(&g_jcB, 1);
        __syncthreads();
        const int j = s_job;
        if (j >= 1024) break;
        const int tb = j >> 8, r8 = j & 255, b = r8 >> 2, nt = r8 & 3;
        const int thr = tb * 128 + 128;
        if (threadIdx.x == 0) {
            const int cb8 = (b >> 3) * 8;
            #pragma unroll
            for (int q = 0; q < 8; q++) {
                while (((volatile int*)g_prog)[cb8 + q] < thr)
                    __nanosleep(128);
            }
            __threadfence();
        }
        __syncthreads();
        gemm_tile(ys + (size_t)(b * TT + tb * 128) * HH,
                  WihB + (size_t)(nt * 128) * HH,
                  biB + nt * 128, bhB + nt * 128,
                  CB + (size_t)(b * TT + tb * 128) * HH + nt * 128,
                  HH, As2, Bs2);
        __syncthreads();
    }
}

// =======================================================================
// Mega kernel: clusters 0..7 = recurrence (8 batches as 2 groups of 4,
// MULTICAST exchange); clusters >= 8 = GEMM workers.
// =======================================================================
__global__ void __launch_bounds__(256, 1) __cluster_dims__(8, 1, 1)
mega(const float* __restrict__ xp, const float* __restrict__ Whh,
     float* __restrict__ ys,
     const float* __restrict__ Ax,  const float* __restrict__ WihA,
     const float* __restrict__ biA, const float* __restrict__ bhA,
     float* __restrict__ CA, int KA,
     const float* __restrict__ WihB, const float* __restrict__ biB,
     const float* __restrict__ bhB,  float* __restrict__ CB,
     int flags)
{
    __shared__ ull2 h_s[2][2][8][4][16];          // [g][buf][chunk][batch][64f]
    __shared__ float redv[8][4][64];
    __shared__ __align__(8) u64 mbar[2][2][8];    // [g][buf][chunk]
    __shared__ u64 As2[8][128];
    __shared__ u64 Bs2[8][128];

    const int tid = threadIdx.x;
    const int cl  = blockIdx.x >> 3;

    if (cl >= 8) {
        // ======================= GEMM role =======================
        if (flags & F_HAVEA) {
            __shared__ int s_job;
            for (;;) {
                if (tid == 0) s_job = atomicAdd(&g_jcA, 1);
                __syncthreads();
                const int j = s_job;
                if (j >= 1024) break;
                const int tb = j >> 8, r8 = j & 255, b = r8 >> 2, nt = r8 & 3;
                gemm_tile(Ax + (size_t)(b * TT + tb * 128) * KA,
                          WihA + (size_t)(nt * 128) * KA,
                          biA + nt * 128, bhA + nt * 128,
                          CA + (size_t)(b * TT + tb * 128) * HH + nt * 128,
                          KA, As2, Bs2);
                __syncthreads();
                __threadfence();
                if (tid == 0) atomicAdd(&g_dA[tb], 1);
                __syncthreads();
            }
        }
        if (flags & F_HAVEB)
            run_phaseB(ys, WihB, biB, bhB, CB, As2, Bs2);
        return;
    }

    // ======================= recurrence role =======================
    const int r     = blockIdx.x & 7;
    const int bg    = cl * 8;
    const int jbase = r * 64;
    const bool gateA = (flags & F_GATEA) != 0;

    const int jp = tid & 31;
    const int kc = tid >> 5;
    const int k0 = kc * 64;

    u64 w[2][32];
    #pragma unroll
    for (int jj = 0; jj < 2; jj++) {
        const float* wrow = &Whh[(size_t)(jbase + jp + jj * 32) * HH + k0];
        #pragma unroll
        for (int kp = 0; kp < 32; kp++) {
            float2 wv = *(const float2*)&wrow[2 * kp];
            w[jj][kp] = pk2(wv.x, wv.y);
        }
    }

    {
        float4* hs = (float4*)h_s;
        for (int i = tid; i < 2 * 2 * 8 * 4 * 16; i += 256)
            hs[i] = make_float4(0.f, 0.f, 0.f, 0.f);
    }
    const uint32_t mb_base = smem_u32(&mbar[0][0][0]);
    const uint32_t hbase   = smem_u32(&h_s[0][0][0][0][0]);
    if (tid < 32) {
        mbar_init(mb_base + (uint32_t)tid * 8u, 1);
        mbar_expect_tx(mb_base + (uint32_t)tid * 8u, 1024u);
    }
    __syncthreads();
    cluster_sync_full();

    uint32_t my_mb[2][2];
    #pragma unroll
    for (int g = 0; g < 2; g++)
        #pragma unroll
        for (int b = 0; b < 2; b++)
            my_mb[g][b] = mb_base + (uint32_t)(((g * 2 + b) * 8 + kc)) * 8u;
    int par[2][2] = {{0, 0}, {0, 0}};

    // multicast push targets: chunk = my rank r, per (g, buf)
    uint32_t mc_dst[2][2], mc_mb[2][2];
    #pragma unroll
    for (int g = 0; g < 2; g++)
        #pragma unroll
        for (int b = 0; b < 2; b++) {
            mc_dst[g][b] = hbase + (uint32_t)g * 16384u + (uint32_t)b * 8192u
                         + (uint32_t)r * 1024u;
            mc_mb[g][b]  = mb_base + (uint32_t)(((g * 2 + b) * 8 + r)) * 8u;
        }
    // gmem staging base for this (cluster, rank): 4 slots x 256 floats
    float* stage = &g_stage[(size_t)((cl * 8 + r) * 4) * 256];

    const int cb = tid >> 6;
    const int cj = tid & 63;
    const float* xp_p[2];
    float*       ys_p[2];
    #pragma unroll
    for (int g = 0; g < 2; g++) {
        xp_p[g] = &xp[((size_t)(bg + g * 4 + cb) * TT) * HH + jbase + cj];
        ys_p[g] = &ys[((size_t)(bg + g * 4 + cb) * TT) * HH + jbase + cj];
    }

    for (int t = 0; t < TT; t++) {
        const int os   = t & 1;
        const int wbuf = os ^ 1;
        const bool push = (t + 1 < TT);

        // gate on phase-A xproj availability (launch 0 only)
        if (gateA && (t & 127) == 0) {
            if (tid == 0) {
                while (((volatile int*)g_dA)[t >> 7] < 256)
                    __nanosleep(128);
                __threadfence();
            }
            __syncthreads();
        }

        float xpv[2];
        xpv[0] = __ldg(xp_p[0]);
        xpv[1] = __ldg(xp_p[1]);

        #pragma unroll
        for (int g = 0; g < 2; g++) {
            if (t > 0) {
                mbar_wait_cluster(my_mb[g][os], par[g][os]);
                if (jp == 0) mbar_expect_tx(my_mb[g][os], 1024u);
                par[g][os] ^= 1;
            }

            const ull2* hb = &h_s[g][os][kc][0][0];
            u64 acc0[4], acc1[4];
            #pragma unroll
            for (int b = 0; b < 4; b++) {
                u64 a0 = 0ull, a1 = 0ull;
                #pragma unroll
                for (int kv = 0; kv < 16; kv++) {
                    ull2 hv = hb[b * 16 + kv];
                    fma2(a0, w[0][2 * kv],     hv.x);
                    fma2(a0, w[0][2 * kv + 1], hv.y);
                    fma2(a1, w[1][2 * kv],     hv.x);
                    fma2(a1, w[1][2 * kv + 1], hv.y);
                }
                acc0[b] = a0; acc1[b] = a1;
            }

            #pragma unroll
            for (int b = 0; b < 4; b++) {
                float2 p0 = upk2(acc0[b]);
                float2 p1 = upk2(acc1[b]);
                redv[kc][b][jp]      = p0.x + p0.y;
                redv[kc][b][jp + 32] = p1.x + p1.y;
            }
            __syncthreads();

            // reduce 8 chunks + xproj + relu; stage to gmem for multicast
            {
                float s = xpv[g];
                #pragma unroll
                for (int c = 0; c < 8; c++) s += redv[c][cb][cj];
                s = fmaxf(s, 0.f);
                stage[(g * 2 + wbuf) * 256 + cb * 64 + cj] = s;
                *ys_p[g] = s;
                ys_p[g] += HH;
            }
            __syncthreads();

            // ONE multicast copy: stage(gmem) -> h_s[g][wbuf][r] in all 8 CTAs
            if (push && tid == 0) {
                __threadfence();            // stage STGs visible at gpu scope
                fence_proxy_async_all();    // ... and to the async proxy
                bulk_copy_mc(mc_dst[g][wbuf],
                             stage + (g * 2 + wbuf) * 256,
                             1024u, mc_mb[g][wbuf], (uint16_t)0xFF);
            }
        }

        // publish recurrence progress every 32 steps
        if ((t & 31) == 31 && tid == 0) {
            __threadfence();
            ((volatile int*)g_prog)[cl * 8 + r] = t + 1;
        }

        xp_p[0] += HH;
        xp_p[1] += HH;
    }

    cluster_sync_full();

    // join the phase-B job queue to absorb the tail
    if (flags & F_HAVEB)
        run_phaseB(ys, WihB, biB, bhB, CB, As2, Bs2);
}

// =======================================================================
__global__ void reset_counters() {
    const int i = threadIdx.x;
    if (i == 0) { g_jcA = 0; g_jcB = 0; }
    if (i < 4) g_dA[i] = 0;
    if (i < 64) g_prog[i] = 0;
}

// =======================================================================
__global__ void proj_kernel(const float* __restrict__ ys,
                            const float* __restrict__ Wout,
                            const float* __restrict__ bout,
                            float* __restrict__ out)
{
    const int b    = blockIdx.x;
    const int c    = threadIdx.y;
    const int lane = threadIdx.x;
    const float* hrow = &ys[((size_t)b * TT + (TT - 1)) * HH];
    const float* wrow = &Wout[(size_t)c * HH];
    float s = 0.f;
    for (int k = lane; k < HH; k += 32) s += hrow[k] * wrow[k];
    #pragma unroll
    for (int o = 16; o > 0; o >>= 1) s += __shfl_down_sync(0xffffffffu, s, o);
    if (lane == 0) out[b * NCLS + c] = s + bout[c];
}

// =======================================================================
extern "C" void kernel_launch(void* const* d_in, const int* in_sizes, int n_in,
                              void* d_out, int out_size)
{
    (void)in_sizes; (void)n_in; (void)out_size;
    const float* x    = (const float*)d_in[0];
    const float* Wih[3] = {(const float*)d_in[1], (const float*)d_in[5], (const float*)d_in[9]};
    const float* Whh[3] = {(const float*)d_in[2], (const float*)d_in[6], (const float*)d_in[10]};
    const float* bih[3] = {(const float*)d_in[3], (const float*)d_in[7], (const float*)d_in[11]};
    const float* bhh[3] = {(const float*)d_in[4], (const float*)d_in[8], (const float*)d_in[12]};
    const float* Wout = (const float*)d_in[13];
    const float* bout = (const float*)d_in[14];
    float* out = (float*)d_out;

    float *xpA = nullptr, *xpB = nullptr, *ysPtr = nullptr;
    cudaGetSymbolAddress((void**)&xpA, g_xpA);
    cudaGetSymbolAddress((void**)&xpB, g_xpB);
    cudaGetSymbolAddress((void**)&ysPtr, g_ys);

    // Layer 0: phase A computes xp0 from x (gating rnn0), phase B computes
    // xp1 from ys0 as it is produced.
    reset_counters<<<1, 64>>>();
    mega<<<144, 256>>>(xpA, Whh[0], ysPtr,
                       x, Wih[0], bih[0], bhh[0], xpA, II,
                       Wih[1], bih[1], bhh[1], xpB,
                       F_HAVEA | F_HAVEB | F_GATEA);

    // Layer 1: xp1 ready; phase B computes xp2 from ys1.
    reset_counters<<<1, 64>>>();
    mega<<<144, 256>>>(xpB, Whh[1], ysPtr,
                       nullptr, nullptr, nullptr, nullptr, nullptr, 0,
                       Wih[2], bih[2], bhh[2], xpA,
                       F_HAVEB);

    // Layer 2: recurrence only.
    mega<<<64, 256>>>(xpA, Whh[2], ysPtr,
                      nullptr, nullptr, nullptr, nullptr, nullptr, 0,
                      nullptr, nullptr, nullptr, nullptr,
                      0);

    proj_kernel<<<64, dim3(32, 5)>>>(ysPtr, Wout, bout, out);
}

// round 13
// speedup vs baseline: 1.1104x; 1.1104x over previous
#include <cuda_runtime.h>
#include <cstdint>
#include <cstddef>

#define BB 64
#define TT 512
#define II 128
#define HH 512
#define NCLS 5

#define F_HAVEA 1
#define F_HAVEB 2
#define F_GATEA 4

typedef unsigned long long u64;
typedef ulonglong2 ull2;

// Scratch — static __device__ arrays per allocation rules.
__device__ float g_xpA[(size_t)BB * TT * HH];
__device__ float g_xpB[(size_t)BB * TT * HH];
__device__ float g_ys[(size_t)BB * TT * HH];

// Cross-CTA coordination (reset by reset_counters before every mega launch).
__device__ int g_jcA;        // phase-A job queue head
__device__ int g_jcB;        // phase-B job queue head
__device__ int g_dA[4];      // phase-A completed-jobs count per t-block
__device__ int g_prog[64];   // recurrence progress per (cluster, rank)

// ---------------- packed f32x2 helpers ----------------
__device__ __forceinline__ u64 pk2(float x, float y) {
    u64 r; asm("mov.b64 %0, {%1,%2};" : "=l"(r) : "f"(x), "f"(y)); return r;
}
__device__ __forceinline__ float2 upk2(u64 v) {
    float2 f; asm("mov.b64 {%0,%1}, %2;" : "=f"(f.x), "=f"(f.y) : "l"(v)); return f;
}
__device__ __forceinline__ void fma2(u64 &d, u64 a, u64 b) {
    asm("fma.rn.f32x2 %0, %1, %2, %0;" : "+l"(d) : "l"(a), "l"(b));
}

// ---------------- cluster / mbarrier helpers ----------------
__device__ __forceinline__ uint32_t smem_u32(const void* p) {
    uint32_t a;
    asm("{ .reg .u64 t; cvta.to.shared.u64 t, %1; cvt.u32.u64 %0, t; }"
        : "=r"(a) : "l"(p));
    return a;
}
__device__ __forceinline__ uint32_t mapa_u32(uint32_t local, uint32_t rank) {
    uint32_t r;
    asm("mapa.shared::cluster.u32 %0, %1, %2;" : "=r"(r) : "r"(local), "r"(rank));
    return r;
}
__device__ __forceinline__ void st_dsmem4(uint32_t addr, float4 v) {
    asm volatile("st.shared::cluster.v4.f32 [%0], {%1,%2,%3,%4};"
                 :: "r"(addr), "f"(v.x), "f"(v.y), "f"(v.z), "f"(v.w) : "memory");
}
__device__ __forceinline__ void mbar_init(uint32_t addr, uint32_t count) {
    asm volatile("mbarrier.init.shared.b64 [%0], %1;" :: "r"(addr), "r"(count) : "memory");
}
__device__ __forceinline__ void mbar_expect_tx(uint32_t addr, uint32_t bytes) {
    asm volatile("mbarrier.arrive.expect_tx.shared.b64 _, [%0], %1;"
                 :: "r"(addr), "r"(bytes) : "memory");
}
__device__ __forceinline__ void mbar_arrive_remote(uint32_t remote_addr) {
    asm volatile("mbarrier.arrive.release.cluster.shared::cluster.b64 _, [%0];"
                 :: "r"(remote_addr) : "memory");
}
__device__ __forceinline__ void bulk_copy_cluster(uint32_t dst_cluster, uint32_t src_cta,
                                                  uint32_t bytes, uint32_t mbar_cluster) {
    asm volatile("cp.async.bulk.shared::cluster.shared::cta.mbarrier::complete_tx::bytes "
                 "[%0], [%1], %2, [%3];"
                 :: "r"(dst_cluster), "r"(src_cta), "r"(bytes), "r"(mbar_cluster) : "memory");
}
__device__ __forceinline__ void mbar_wait_cluster(uint32_t addr, uint32_t parity) {
    asm volatile(
        "{\n\t"
        ".reg .pred P;\n\t"
        "WLP%=:\n\t"
        "mbarrier.try_wait.parity.acquire.cluster.shared::cta.b64 P, [%0], %1, 0x989680;\n\t"
        "@P bra WDN%=;\n\t"
        "bra WLP%=;\n\t"
        "WDN%=:\n\t"
        "}"
        :: "r"(addr), "r"(parity) : "memory");
}
__device__ __forceinline__ void fence_proxy_async_cta() {
    asm volatile("fence.proxy.async.shared::cta;" ::: "memory");
}
__device__ __forceinline__ void cluster_sync_full() {
    asm volatile("barrier.cluster.arrive.aligned;" ::: "memory");
    asm volatile("barrier.cluster.wait.aligned;" ::: "memory");
}

// =======================================================================
// One 128x128 GEMM tile: C = A[0:128,0:K] @ W[0:128,0:K]^T + b1 + b2.
// =======================================================================
__device__ __forceinline__ void gemm_tile(
    const float* __restrict__ A, const float* __restrict__ W,
    const float* __restrict__ b1, const float* __restrict__ b2,
    float* __restrict__ C, int K,
    u64 (*As2)[128], u64 (*Bs2)[128])
{
    const int tid = threadIdx.x;
    const int tx = tid & 15;
    const int ty = tid >> 4;
    const int r0  = tid >> 2;
    const int kq0 = tid & 3;

    u64 acc[8][8];
    #pragma unroll
    for (int i = 0; i < 8; i++)
        #pragma unroll
        for (int j = 0; j < 8; j++) acc[i][j] = 0ull;

    const float* pa0 = &A[(size_t)r0        * K + kq0 * 4];
    const float* pa1 = &A[(size_t)(64 + r0) * K + kq0 * 4];
    const float* pw0 = &W[(size_t)r0        * K + kq0 * 4];
    const float* pw1 = &W[(size_t)(64 + r0) * K + kq0 * 4];

    const int ktiles = K >> 4;
    float4 a0 = *(const float4*)pa0;
    float4 a1 = *(const float4*)pa1;
    float4 w0 = *(const float4*)pw0;
    float4 w1 = *(const float4*)pw1;

    for (int kt = 0; kt < ktiles; kt++) {
        __syncthreads();
        As2[kq0 * 2][r0]          = pk2(a0.x, a0.y);
        As2[kq0 * 2 + 1][r0]      = pk2(a0.z, a0.w);
        As2[kq0 * 2][64 + r0]     = pk2(a1.x, a1.y);
        As2[kq0 * 2 + 1][64 + r0] = pk2(a1.z, a1.w);
        Bs2[kq0 * 2][r0]          = pk2(w0.x, w0.y);
        Bs2[kq0 * 2 + 1][r0]      = pk2(w0.z, w0.w);
        Bs2[kq0 * 2][64 + r0]     = pk2(w1.x, w1.y);
        Bs2[kq0 * 2 + 1][64 + r0] = pk2(w1.z, w1.w);
        __syncthreads();

        if (kt + 1 < ktiles) {
            const int kb = (kt + 1) * 16;
            a0 = *(const float4*)(pa0 + kb);
            a1 = *(const float4*)(pa1 + kb);
            w0 = *(const float4*)(pw0 + kb);
            w1 = *(const float4*)(pw1 + kb);
        }

        #pragma unroll
        for (int k2 = 0; k2 < 8; k2++) {
            u64 af[8], bf[8];
            #pragma unroll
            for (int i = 0; i < 8; i++) af[i] = As2[k2][ty + 16 * i];
            #pragma unroll
            for (int j = 0; j < 8; j++) bf[j] = Bs2[k2][tx + 16 * j];
            #pragma unroll
            for (int i = 0; i < 8; i++)
                #pragma unroll
                for (int j = 0; j < 8; j++)
                    fma2(acc[i][j], af[i], bf[j]);
        }
    }

    float bias8[8];
    #pragma unroll
    for (int j = 0; j < 8; j++) {
        int n = tx + 16 * j;
        bias8[j] = b1[n] + b2[n];
    }
    #pragma unroll
    for (int i = 0; i < 8; i++) {
        const size_t m = (size_t)(ty + 16 * i);
        #pragma unroll
        for (int j = 0; j < 8; j++) {
            float2 p = upk2(acc[i][j]);
            C[m * HH + tx + 16 * j] = p.x + p.y + bias8[j];
        }
    }
}

// Run phase-B jobs (xproj of next layer from ys, K=512, gated on g_prog).
__device__ void run_phaseB(const float* __restrict__ ys,
                           const float* __restrict__ WihB,
                           const float* __restrict__ biB,
                           const float* __restrict__ bhB,
                           float* __restrict__ CB,
                           u64 (*As2)[128], u64 (*Bs2)[128])
{
    __shared__ int s_job;
    for (;;) {
        if (threadIdx.x == 0)
            s_job = atomicAdd(&g_jcB, 1);
        __syncthreads();
        const int j = s_job;
        if (j >= 1024) break;
        const int tb = j >> 8, r8 = j & 255, b = r8 >> 2, nt = r8 & 3;
        const int thr = tb * 128 + 128;
        if (threadIdx.x == 0) {
            const int cb8 = (b >> 3) * 8;
            #pragma unroll
            for (int q = 0; q < 8; q++) {
                while (((volatile int*)g_prog)[cb8 + q] < thr)
                    __nanosleep(128);
            }
            __threadfence();
        }
        __syncthreads();
        gemm_tile(ys + (size_t)(b * TT + tb * 128) * HH,
                  WihB + (size_t)(nt * 128) * HH,
                  biB + nt * 128, bhB + nt * 128,
                  CB + (size_t)(b * TT + tb * 128) * HH + nt * 128,
                  HH, As2, Bs2);
        __syncthreads();
    }
}

// =======================================================================
// Mega kernel: clusters 0..7 = recurrence; clusters >= 8 = GEMM workers.
// Recurrence = R9 two-group scheme with HYBRID exchange:
//   group 0: bulk-engine 1KB copies (8/step), tx-counted mbarriers.
//   group 1: direct st.shared::cluster.v4 by 64 issuer lanes + one
//            release-arrive per peer (count-1 mbarriers, no expect_tx).
// Halves the per-SM bulk-engine load (16 -> 8 copies/step) which R4..R9
// data shows is the step pacer (~290 cyc/copy).
// =======================================================================
__global__ void __launch_bounds__(256, 1) __cluster_dims__(8, 1, 1)
mega(const float* __restrict__ xp, const float* __restrict__ Whh,
     float* __restrict__ ys,
     const float* __restrict__ Ax,  const float* __restrict__ WihA,
     const float* __restrict__ biA, const float* __restrict__ bhA,
     float* __restrict__ CA, int KA,
     const float* __restrict__ WihB, const float* __restrict__ biB,
     const float* __restrict__ bhB,  float* __restrict__ CB,
     int flags)
{
    __shared__ ull2 h_s[2][2][8][4][16];       // [g][buf][chunk][batch][64f] 32KB
    __shared__ float redv[8][4][64];
    __shared__ __align__(16) float out_s[2][4][64];   // [buf][batch][col], g0 only
    __shared__ __align__(8) u64 mbar[2][2][8];  // [g][buf][chunk]
    __shared__ u64 As2[8][128];
    __shared__ u64 Bs2[8][128];

    const int tid = threadIdx.x;
    const int cl  = blockIdx.x >> 3;

    if (cl >= 8) {
        // ======================= GEMM role =======================
        if (flags & F_HAVEA) {
            __shared__ int s_job;
            for (;;) {
                if (tid == 0) s_job = atomicAdd(&g_jcA, 1);
                __syncthreads();
                const int j = s_job;
                if (j >= 1024) break;
                const int tb = j >> 8, r8 = j & 255, b = r8 >> 2, nt = r8 & 3;
                gemm_tile(Ax + (size_t)(b * TT + tb * 128) * KA,
                          WihA + (size_t)(nt * 128) * KA,
                          biA + nt * 128, bhA + nt * 128,
                          CA + (size_t)(b * TT + tb * 128) * HH + nt * 128,
                          KA, As2, Bs2);
                __syncthreads();
                __threadfence();
                if (tid == 0) atomicAdd(&g_dA[tb], 1);
                __syncthreads();
            }
        }
        if (flags & F_HAVEB)
            run_phaseB(ys, WihB, biB, bhB, CB, As2, Bs2);
        return;
    }

    // ======================= recurrence role =======================
    const int r     = blockIdx.x & 7;
    const int bg    = cl * 8;
    const int jbase = r * 64;
    const bool gateA = (flags & F_GATEA) != 0;

    const int jp = tid & 31;
    const int kc = tid >> 5;
    const int k0 = kc * 64;

    u64 w[2][32];
    #pragma unroll
    for (int jj = 0; jj < 2; jj++) {
        const float* wrow = &Whh[(size_t)(jbase + jp + jj * 32) * HH + k0];
        #pragma unroll
        for (int kp = 0; kp < 32; kp++) {
            float2 wv = *(const float2*)&wrow[2 * kp];
            w[jj][kp] = pk2(wv.x, wv.y);
        }
    }

    {
        float4* hs = (float4*)h_s;
        for (int i = tid; i < 2 * 2 * 8 * 4 * 16; i += 256)
            hs[i] = make_float4(0.f, 0.f, 0.f, 0.f);
    }
    const uint32_t mb_base = smem_u32(&mbar[0][0][0]);
    const uint32_t hbase   = smem_u32(&h_s[0][0][0][0][0]);
    const uint32_t obase   = smem_u32(&out_s[0][0][0]);
    if (tid < 32) {
        mbar_init(mb_base + (uint32_t)tid * 8u, 1);
        if (tid < 16)                                   // g0 mbars: tx-counted
            mbar_expect_tx(mb_base + (uint32_t)tid * 8u, 1024u);
    }
    __syncthreads();
    cluster_sync_full();

    uint32_t my_mb[2][2];
    #pragma unroll
    for (int g = 0; g < 2; g++)
        #pragma unroll
        for (int b = 0; b < 2; b++)
            my_mb[g][b] = mb_base + (uint32_t)(((g * 2 + b) * 8 + kc)) * 8u;
    int par[2][2] = {{0, 0}, {0, 0}};

    // g0 engine copy targets (tid < 8): peer q = tid, chunk = rank r
    uint32_t dst_q = 0;
    uint32_t rmb0[2];                 // remote g0 mbar [buf] on peer q
    uint32_t amb1[2];                 // remote g1 mbar [buf] on peer q (arrive)
    if (tid < 8) {
        const uint32_t q = (uint32_t)tid;
        dst_q = mapa_u32(hbase, q) + (uint32_t)r * 1024u;
        #pragma unroll
        for (int b = 0; b < 2; b++) {
            rmb0[b] = mapa_u32(mb_base + (uint32_t)((b * 8 + r)) * 8u, q);
            amb1[b] = mapa_u32(mb_base + (uint32_t)(((2 + b) * 8 + r)) * 8u, q);
        }
    }

    const int cb = tid >> 6;
    const int cj = tid & 63;
    const float* xp_p[2];
    float*       ys_p[2];
    #pragma unroll
    for (int g = 0; g < 2; g++) {
        xp_p[g] = &xp[((size_t)(bg + g * 4 + cb) * TT) * HH + jbase + cj];
        ys_p[g] = &ys[((size_t)(bg + g * 4 + cb) * TT) * HH + jbase + cj];
    }

    // g1 direct-store targets: all 64 issuer lanes ((tid&3)==0 within warp
    // quad mapping below), 8 peers each. Offset inside h_s (g=1 region):
    //   16384 + wbuf*8192 + r*1024 + cb*256 + (cj&~3)*4
    const bool issuer = ((jp & 3) == 0);
    const unsigned lane_base = (unsigned)(jp & ~3);
    uint32_t sdst[8];
    {
        const uint32_t loc = 16384u + (uint32_t)r * 1024u
                           + (uint32_t)cb * 256u + (uint32_t)(cj & ~3) * 4u;
        #pragma unroll
        for (int q = 0; q < 8; q++)
            sdst[q] = mapa_u32(hbase, (uint32_t)q) + loc;
    }

    for (int t = 0; t < TT; t++) {
        const int os   = t & 1;
        const int wbuf = os ^ 1;
        const bool push = (t + 1 < TT);

        // gate on phase-A xproj availability (launch 0 only)
        if (gateA && (t & 127) == 0) {
            if (tid == 0) {
                while (((volatile int*)g_dA)[t >> 7] < 256)
                    __nanosleep(128);
                __threadfence();
            }
            __syncthreads();
        }

        float xpv[2];
        xpv[0] = __ldg(xp_p[0]);
        xpv[1] = __ldg(xp_p[1]);

        // =================== GROUP 0 (bulk engine) ===================
        if (t > 0) {
            mbar_wait_cluster(my_mb[0][os], par[0][os]);
            if (jp == 0) mbar_expect_tx(my_mb[0][os], 1024u);
            par[0][os] ^= 1;
        }
        {
            const ull2* hb = &h_s[0][os][kc][0][0];
            u64 acc0[4], acc1[4];
            #pragma unroll
            for (int b = 0; b < 4; b++) {
                u64 a0 = 0ull, a1 = 0ull;
                #pragma unroll
                for (int kv = 0; kv < 16; kv++) {
                    ull2 hv = hb[b * 16 + kv];
                    fma2(a0, w[0][2 * kv],     hv.x);
                    fma2(a0, w[0][2 * kv + 1], hv.y);
                    fma2(a1, w[1][2 * kv],     hv.x);
                    fma2(a1, w[1][2 * kv + 1], hv.y);
                }
                acc0[b] = a0; acc1[b] = a1;
            }
            #pragma unroll
            for (int b = 0; b < 4; b++) {
                float2 p0 = upk2(acc0[b]);
                float2 p1 = upk2(acc1[b]);
                redv[kc][b][jp]      = p0.x + p0.y;
                redv[kc][b][jp + 32] = p1.x + p1.y;
            }
        }
        __syncthreads();
        {
            float s = xpv[0];
            #pragma unroll
            for (int c = 0; c < 8; c++) s += redv[c][cb][cj];
            s = fmaxf(s, 0.f);
            out_s[os][cb][cj] = s;
            *ys_p[0] = s;
            ys_p[0] += HH;
        }
        __syncthreads();
        if (push && tid < 8) {
            fence_proxy_async_cta();
            bulk_copy_cluster(dst_q + (uint32_t)wbuf * 8192u,
                              obase + (uint32_t)os * 1024u,
                              1024u, rmb0[wbuf]);
        }

        // =================== GROUP 1 (direct stores) ===================
        if (t > 0) {
            mbar_wait_cluster(my_mb[1][os], par[1][os]);
            par[1][os] ^= 1;
        }
        {
            const ull2* hb = &h_s[1][os][kc][0][0];
            u64 acc0[4], acc1[4];
            #pragma unroll
            for (int b = 0; b < 4; b++) {
                u64 a0 = 0ull, a1 = 0ull;
                #pragma unroll
                for (int kv = 0; kv < 16; kv++) {
                    ull2 hv = hb[b * 16 + kv];
                    fma2(a0, w[0][2 * kv],     hv.x);
                    fma2(a0, w[0][2 * kv + 1], hv.y);
                    fma2(a1, w[1][2 * kv],     hv.x);
                    fma2(a1, w[1][2 * kv + 1], hv.y);
                }
                acc0[b] = a0; acc1[b] = a1;
            }
            #pragma unroll
            for (int b = 0; b < 4; b++) {
                float2 p0 = upk2(acc0[b]);
                float2 p1 = upk2(acc1[b]);
                redv[kc][b][jp]      = p0.x + p0.y;
                redv[kc][b][jp + 32] = p1.x + p1.y;
            }
        }
        __syncthreads();
        {
            float s = xpv[1];
            #pragma unroll
            for (int c = 0; c < 8; c++) s += redv[c][cb][cj];
            s = fmaxf(s, 0.f);
            *ys_p[1] = s;
            ys_p[1] += HH;

            // direct remote stores of this CTA's g1 slice to all peers
            if (push) {
                float4 v;
                v.x = __shfl_sync(0xffffffffu, s, lane_base);
                v.y = __shfl_sync(0xffffffffu, s, lane_base + 1);
                v.z = __shfl_sync(0xffffffffu, s, lane_base + 2);
                v.w = __shfl_sync(0xffffffffu, s, lane_base + 3);
                if (issuer) {
                    const uint32_t boff = (uint32_t)wbuf * 8192u;
                    #pragma unroll
                    for (int q = 0; q < 8; q++)
                        st_dsmem4(sdst[q] + boff, v);
                }
            }
        }
        __syncthreads();   // all g1 stores issued (happens-before the release)
        if (push && tid < 8)
            mbar_arrive_remote(amb1[wbuf]);

        // publish recurrence progress every 32 steps
        if ((t & 31) == 31 && tid == 0) {
            __threadfence();
            ((volatile int*)g_prog)[cl * 8 + r] = t + 1;
        }

        xp_p[0] += HH;
        xp_p[1] += HH;
    }

    cluster_sync_full();

    // join the phase-B job queue to absorb the tail
    if (flags & F_HAVEB)
        run_phaseB(ys, WihB, biB, bhB, CB, As2, Bs2);
}

// =======================================================================
__global__ void reset_counters() {
    const int i = threadIdx.x;
    if (i == 0) { g_jcA = 0; g_jcB = 0; }
    if (i < 4) g_dA[i] = 0;
    if (i < 64) g_prog[i] = 0;
}

// =======================================================================
__global__ void proj_kernel(const float* __restrict__ ys,
                            const float* __restrict__ Wout,
                            const float* __restrict__ bout,
                            float* __restrict__ out)
{
    const int b    = blockIdx.x;
    const int c    = threadIdx.y;
    const int lane = threadIdx.x;
    const float* hrow = &ys[((size_t)b * TT + (TT - 1)) * HH];
    const float* wrow = &Wout[(size_t)c * HH];
    float s = 0.f;
    for (int k = lane; k < HH; k += 32) s += hrow[k] * wrow[k];
    #pragma unroll
    for (int o = 16; o > 0; o >>= 1) s += __shfl_down_sync(0xffffffffu, s, o);
    if (lane == 0) out[b * NCLS + c] = s + bout[c];
}

// =======================================================================
extern "C" void kernel_launch(void* const* d_in, const int* in_sizes, int n_in,
                              void* d_out, int out_size)
{
    (void)in_sizes; (void)n_in; (void)out_size;
    const float* x    = (const float*)d_in[0];
    const float* Wih[3] = {(const float*)d_in[1], (const float*)d_in[5], (const float*)d_in[9]};
    const float* Whh[3] = {(const float*)d_in[2], (const float*)d_in[6], (const float*)d_in[10]};
    const float* bih[3] = {(const float*)d_in[3], (const float*)d_in[7], (const float*)d_in[11]};
    const float* bhh[3] = {(const float*)d_in[4], (const float*)d_in[8], (const float*)d_in[12]};
    const float* Wout = (const float*)d_in[13];
    const float* bout = (const float*)d_in[14];
    float* out = (float*)d_out;

    float *xpA = nullptr, *xpB = nullptr, *ysPtr = nullptr;
    cudaGetSymbolAddress((void**)&xpA, g_xpA);
    cudaGetSymbolAddress((void**)&xpB, g_xpB);
    cudaGetSymbolAddress((void**)&ysPtr, g_ys);

    // Layer 0: phase A computes xp0 from x (gating rnn0), phase B computes
    // xp1 from ys0 as it is produced.
    reset_counters<<<1, 64>>>();
    mega<<<144, 256>>>(xpA, Whh[0], ysPtr,
                       x, Wih[0], bih[0], bhh[0], xpA, II,
                       Wih[1], bih[1], bhh[1], xpB,
                       F_HAVEA | F_HAVEB | F_GATEA);

    // Layer 1: xp1 ready; phase B computes xp2 from ys1.
    reset_counters<<<1, 64>>>();
    mega<<<144, 256>>>(xpB, Whh[1], ysPtr,
                       nullptr, nullptr, nullptr, nullptr, nullptr, 0,
                       Wih[2], bih[2], bhh[2], xpA,
                       F_HAVEB);

    // Layer 2: recurrence only.
    mega<<<64, 256>>>(xpA, Whh[2], ysPtr,
                      nullptr, nullptr, nullptr, nullptr, nullptr, 0,
                      nullptr, nullptr, nullptr, nullptr,
                      0);

    proj_kernel<<<64, dim3(32, 5)>>>(ysPtr, Wout, bout, out);
}